// round 14
// baseline (speedup 1.0000x reference)
#include <cuda_runtime.h>
#include <cstdint>

#define NSEQ 2048
#define SCALEQ 0.18033688011112042f   // (1/sqrt(64)) * log2(e)

static const size_t ATT_OFF = 2097152;   // 16*2048*64

// smem float offsets
#define QP    0        // Q stage / P row buf 0: 128 x 68
#define P1R   8704     // P row buf 1: 128 x 68
#define PF0   17408    // P frag buf 0: 4 groups x 2048
#define PF1   25600    // P frag buf 1
#define KS0   33792    // pass B K: 64 x 68
#define KS1   38144
#define VS0   42496    // pass B V: 64 x 72 (double buffered)
#define VS1   47104
#define MSK   51712    // 64 u32
#define SLP   51776    // 4 x 128 partial row sums
#define RRI   52288    // 128
#define SMEMF 52416    // 209,664 B
// pass A mega-K buffers (128 x 68 each), aliasing pass-B-only regions:
#define KA0   8704     // = P1R
#define KA1   17408    // = PF0..PF1 (8704 <= 16384)

#define KVELEMS (16 * 2048 * 64)
__device__ float g_kc[KVELEMS];   // K pre-converted to tf32 bits
__device__ float g_vc[KVELEMS];   // V pre-converted to tf32 bits

__device__ __forceinline__ uint32_t smem_u32(const void* p) {
    uint32_t a;
    asm("{ .reg .u64 t; cvta.to.shared.u64 t, %1; cvt.u32.u64 %0, t; }" : "=r"(a) : "l"(p));
    return a;
}
__device__ __forceinline__ float ex2f_(float x) {
    float y; asm("ex2.approx.ftz.f32 %0, %1;" : "=f"(y) : "f"(x)); return y;
}
__device__ __forceinline__ unsigned cvt_tf32(float x) {
    unsigned y; asm("cvt.rna.tf32.f32 %0, %1;" : "=r"(y) : "f"(x)); return y;
}
__device__ __forceinline__ void mma_tf32(float c[4],
                                         unsigned a0, unsigned a1, unsigned a2, unsigned a3,
                                         unsigned b0, unsigned b1) {
    asm volatile(
        "mma.sync.aligned.m16n8k8.row.col.f32.tf32.tf32.f32 "
        "{%0,%1,%2,%3}, {%4,%5,%6,%7}, {%8,%9}, {%0,%1,%2,%3};"
        : "+f"(c[0]), "+f"(c[1]), "+f"(c[2]), "+f"(c[3])
        : "r"(a0), "r"(a1), "r"(a2), "r"(a3), "r"(b0), "r"(b1));
}

__device__ __forceinline__ void cp16(uint32_t dst, const void* src) {
    asm volatile("cp.async.cg.shared.global [%0], [%1], 16;" :: "r"(dst), "l"(src) : "memory");
}
#define CP_COMMIT() asm volatile("cp.async.commit_group;" ::: "memory")
#define CP_WAIT0()  asm volatile("cp.async.wait_group 0;" ::: "memory")

// =============== Kernel 0: pre-convert K,V to tf32 bits ===============
__global__ void __launch_bounds__(512, 4)
kv_cvt(const float* __restrict__ k, const float* __restrict__ v) {
    int idx = (blockIdx.x * 512 + threadIdx.x) * 4;
    if (idx < KVELEMS) {
        float4 tk = *(const float4*)(k + idx);
        float4 tv = *(const float4*)(v + idx);
        uint4 uk, uv;
        uk.x = cvt_tf32(tk.x); uk.y = cvt_tf32(tk.y); uk.z = cvt_tf32(tk.z); uk.w = cvt_tf32(tk.w);
        uv.x = cvt_tf32(tv.x); uv.y = cvt_tf32(tv.y); uv.z = cvt_tf32(tv.z); uv.w = cvt_tf32(tv.w);
        *(uint4*)(g_kc + idx) = uk;
        *(uint4*)(g_vc + idx) = uv;
    }
}

// 64x64 fp32 tile -> smem (512 thr x 2 chunks of 16B)
__device__ __forceinline__ void issue_tile64(uint32_t buf, const float* src, int tid, int strideB) {
#pragma unroll
    for (int it = 0; it < 2; ++it) {
        int idx = tid + it * 512;
        int row = idx >> 4, c16 = (idx & 15) << 4;
        cp16(buf + row * strideB + c16, (const char*)src + row * 256 + c16);
    }
}
// 128x64 fp32 tile -> smem (512 thr x 4 chunks)
__device__ __forceinline__ void issue_tile128(uint32_t buf, const float* src, int tid, int strideB) {
#pragma unroll
    for (int it = 0; it < 4; ++it) {
        int idx = tid + it * 512;
        int row = idx >> 4, c16 = (idx & 15) << 4;
        cp16(buf + row * strideB + c16, (const char*)src + row * 256 + c16);
    }
}

// S warp-tile: rows wm*32..+31, keys keybase + nt*8 (NT n-subtiles); K already tf32 bits
template <int NT>
__device__ __forceinline__ void compute_S_nt(const unsigned aq[8][2][4], const float* __restrict__ Ks,
                                             int keybase, int g, int tig, float c[2][NT][4]) {
#pragma unroll
    for (int ms = 0; ms < 2; ++ms)
#pragma unroll
        for (int nt = 0; nt < NT; ++nt)
#pragma unroll
            for (int e = 0; e < 4; ++e) c[ms][nt][e] = 0.f;
#pragma unroll
    for (int ks = 0; ks < 8; ++ks) {
#pragma unroll
        for (int nt = 0; nt < NT; ++nt) {
            const float* kr = Ks + (keybase + nt * 8 + g) * 68 + ks * 8;
            unsigned b0 = __float_as_uint(kr[tig]);
            unsigned b1 = __float_as_uint(kr[tig + 4]);
            mma_tf32(c[0][nt], aq[ks][0][0], aq[ks][0][1], aq[ks][0][2], aq[ks][0][3], b0, b1);
            mma_tf32(c[1][nt], aq[ks][1][0], aq[ks][1][1], aq[ks][1][2], aq[ks][1][3], b0, b1);
        }
    }
}

__global__ void __launch_bounds__(512, 1)
lg14_kernel(const float* __restrict__ q, const int* __restrict__ mask,
            float* __restrict__ out) {
    extern __shared__ float sm[];
    const uint32_t sbu = smem_u32(sm);
    const int tid = threadIdx.x;
    const int w = tid >> 5, lane = tid & 31;
    const int wm = w & 3, wn = w >> 2;           // 4 row groups x 4 key groups
    const int g = lane >> 2, tig = lane & 3;

    const int bh = blockIdx.y, b = bh >> 2;      // H = 4
    const int i0 = blockIdx.x * 128;
    const float* qg = q + ((size_t)bh * NSEQ + i0) * 64;
    const float* kg = g_kc + (size_t)bh * NSEQ * 64;
    const float* vg = g_vc + (size_t)bh * NSEQ * 64;
    const int* mg = mask + (size_t)b * NSEQ;
    float* attg = out + ATT_OFF + ((size_t)bh * NSEQ + i0) * NSEQ;
    const unsigned* mw = (const unsigned*)(sm + MSK);

    // ---- prologue: Q (scaled, tf32) into QP; mask bitwords; K mega-tile 0 ----
#pragma unroll
    for (int it = 0; it < 4; ++it) {
        int idx = tid + it * 512;
        int r = idx >> 4, c4 = (idx & 15) << 2;
        float4 t = *(const float4*)(qg + r * 64 + c4);
        uint4 u;
        u.x = cvt_tf32(t.x * SCALEQ); u.y = cvt_tf32(t.y * SCALEQ);
        u.z = cvt_tf32(t.z * SCALEQ); u.w = cvt_tf32(t.w * SCALEQ);
        *(uint4*)(sm + QP + r * 68 + c4) = u;
    }
    if (tid < 64) {
        unsigned bits = 0;
#pragma unroll 8
        for (int r = 0; r < 32; ++r) bits |= (mg[tid * 32 + r] != 0 ? 1u : 0u) << r;
        ((unsigned*)(sm + MSK))[tid] = bits;
    }
    issue_tile128(sbu + KA0 * 4, kg, tid, 272);
    CP_COMMIT();
    __syncthreads();

    // Q A-fragments register-resident for both passes
    unsigned aq[8][2][4];
#pragma unroll
    for (int ks = 0; ks < 8; ++ks)
#pragma unroll
        for (int ms = 0; ms < 2; ++ms) {
            const float* qr = sm + QP + (wm * 32 + ms * 16 + g) * 68 + ks * 8;
            aq[ks][ms][0] = __float_as_uint(qr[tig]);
            aq[ks][ms][1] = __float_as_uint(qr[8 * 68 + tig]);
            aq[ks][ms][2] = __float_as_uint(qr[tig + 4]);
            aq[ks][ms][3] = __float_as_uint(qr[8 * 68 + tig + 4]);
        }

    // =================== Pass A: row sums, 128-key mega-tiles (16 iters) ===================
    float l[4] = {0.f, 0.f, 0.f, 0.f};   // slot s: row wm*32 + (s>>1)*16 + g + (s&1)*8
    for (int j = 0; j < 16; ++j) {
        CP_WAIT0();
        __syncthreads();
        if (j < 15) {
            issue_tile128(sbu + (((j + 1) & 1) ? KA1 : KA0) * 4, kg + (size_t)(j + 1) * 128 * 64, tid, 272);
            CP_COMMIT();
        }
        float c[2][4][4];
        compute_S_nt<4>(aq, sm + ((j & 1) ? KA1 : KA0), wn * 32, g, tig, c);

        unsigned wbits = mw[4 * j + wn];
#pragma unroll
        for (int ms = 0; ms < 2; ++ms)
#pragma unroll
            for (int nt = 0; nt < 4; ++nt) {
                int base = nt * 8 + 2 * tig;
                float e0 = ((wbits >> base) & 1u) ? ex2f_(c[ms][nt][0]) : 0.f;
                float e1 = ((wbits >> (base + 1)) & 1u) ? ex2f_(c[ms][nt][1]) : 0.f;
                float e2 = ((wbits >> base) & 1u) ? ex2f_(c[ms][nt][2]) : 0.f;
                float e3 = ((wbits >> (base + 1)) & 1u) ? ex2f_(c[ms][nt][3]) : 0.f;
                l[ms * 2] += e0 + e1;
                l[ms * 2 + 1] += e2 + e3;
            }
    }

    // K(0), V(0) prefetch (KS0/VS0 regions untouched by pass A)
    issue_tile64(sbu + KS0 * 4, kg, tid, 272);
    issue_tile64(sbu + VS0 * 4, vg, tid, 288);
    CP_COMMIT();

    // reduce l: tig lanes, then wn groups via smem
#pragma unroll
    for (int s = 0; s < 4; ++s) {
        l[s] += __shfl_xor_sync(0xffffffffu, l[s], 1);
        l[s] += __shfl_xor_sync(0xffffffffu, l[s], 2);
    }
    if (tig == 0) {
#pragma unroll
        for (int s = 0; s < 4; ++s) {
            int row = wm * 32 + (s >> 1) * 16 + g + (s & 1) * 8;
            sm[SLP + wn * 128 + row] = l[s];
        }
    }
    __syncthreads();
    if (tid < 128) {
        float lt = sm[SLP + tid] + sm[SLP + 128 + tid] + sm[SLP + 256 + tid] + sm[SLP + 384 + tid];
        sm[RRI + tid] = 1.0f / lt;
    }
    __syncthreads();

    float rri[4];
#pragma unroll
    for (int s = 0; s < 4; ++s)
        rri[s] = sm[RRI + wm * 32 + (s >> 1) * 16 + g + (s & 1) * 8];

    // =================== Pass B: pipelined; P dual-staged (row + fragment-major) ===================
    float o[2][2][4];
#pragma unroll
    for (int ms = 0; ms < 2; ++ms)
#pragma unroll
        for (int nt = 0; nt < 2; ++nt)
#pragma unroll
            for (int e = 0; e < 4; ++e) o[ms][nt][e] = 0.f;

#define PROW(jj) (sm + (((jj) & 1) ? P1R : QP))
#define PFRG(jj) (sm + (((jj) & 1) ? PF1 : PF0) + wm * 2048)
#define VBUF(jj) (sm + (((jj) & 1) ? VS1 : VS0))

    const int tigf0 = (2 * tig) & 3;          // fragment slot pair base
    const int fcomp = (tig >= 2) ? 2 : 0;     // component offset within float4

    // ---- prologue iteration (j = 0): S(0) -> P(0) ----
    {
        CP_WAIT0();
        __syncthreads();   // K(0), V(0) arrived
        issue_tile64(sbu + KS1 * 4, kg + (size_t)64 * 64, tid, 272);
        CP_COMMIT();

        float c[2][2][4];
        compute_S_nt<2>(aq, sm + KS0, wn * 16, g, tig, c);
        unsigned wbits = mw[wn >> 1];
        float* Pr = PROW(0);
        float* Pf = PFRG(0);
#pragma unroll
        for (int ms = 0; ms < 2; ++ms)
#pragma unroll
            for (int nt = 0; nt < 2; ++nt) {
                int base = (wn & 1) * 16 + nt * 8 + 2 * tig;
                float p0 = ((wbits >> base) & 1u) ? ex2f_(c[ms][nt][0]) * rri[2 * ms] : 0.f;
                float p1 = ((wbits >> (base + 1)) & 1u) ? ex2f_(c[ms][nt][1]) * rri[2 * ms] : 0.f;
                float p2 = ((wbits >> base) & 1u) ? ex2f_(c[ms][nt][2]) * rri[2 * ms + 1] : 0.f;
                float p3 = ((wbits >> (base + 1)) & 1u) ? ex2f_(c[ms][nt][3]) * rri[2 * ms + 1] : 0.f;
                unsigned u0 = cvt_tf32(p0), u1 = cvt_tf32(p1), u2 = cvt_tf32(p2), u3 = cvt_tf32(p3);
                int lr = wm * 32 + ms * 16 + g, lc = wn * 16 + nt * 8 + 2 * tig;
                *(uint2*)(Pr + lr * 68 + lc) = make_uint2(u0, u1);
                *(uint2*)(Pr + (lr + 8) * 68 + lc) = make_uint2(u2, u3);
                int kb = wn * 2 + nt;
                float* fb = Pf + ((ms * 8 + kb) * 4 + tigf0) * 32 + g * 4 + fcomp;
                *(uint2*)fb = make_uint2(u0, u2);
                *(uint2*)(fb + 32) = make_uint2(u1, u3);
            }
    }

    // ---- main loop: j = 1..31 ----
    for (int j = 1; j < 32; ++j) {
        CP_WAIT0();
        __syncthreads();   // K(j), V(j-1) arrived; P(j-1) staged; bufs (j&1) free

        if (j < 31)
            issue_tile64(sbu + (((j + 1) & 1) ? KS1 : KS0) * 4, kg + (size_t)(j + 1) * 64 * 64, tid, 272);
        issue_tile64(sbu + ((j & 1) ? VS1 : VS0) * 4, vg + (size_t)j * 64 * 64, tid, 288);
        CP_COMMIT();

        // attention store for tile j-1 (coalesced 256B row segments)
        {
            const float* Pr = PROW(j - 1);
#pragma unroll
            for (int it = 0; it < 4; ++it) {
                int idx = tid + it * 512;
                int row = idx >> 4, c4 = (idx & 15) << 2;
                float4 pv = *(const float4*)(Pr + row * 68 + c4);
                *(float4*)(attg + (size_t)row * NSEQ + (j - 1) * 64 + c4) = pv;
            }
        }

        // PV(j-1): A-frags via LDS.128 from fragment-major P
        {
            const float* Pf = PFRG(j - 1);
            const float* Vs = VBUF(j - 1);
#pragma unroll
            for (int kb = 0; kb < 8; ++kb) {
                uint4 fa0 = *(const uint4*)(Pf + ((0 * 8 + kb) * 4 + tig) * 32 + g * 4);
                uint4 fa1 = *(const uint4*)(Pf + ((1 * 8 + kb) * 4 + tig) * 32 + g * 4);
#pragma unroll
                for (int nt = 0; nt < 2; ++nt) {
                    unsigned b0 = __float_as_uint(Vs[(kb * 8 + tig) * 72 + wn * 16 + nt * 8 + g]);
                    unsigned b1 = __float_as_uint(Vs[(kb * 8 + tig + 4) * 72 + wn * 16 + nt * 8 + g]);
                    mma_tf32(o[0][nt], fa0.x, fa0.y, fa0.z, fa0.w, b0, b1);
                    mma_tf32(o[1][nt], fa1.x, fa1.y, fa1.z, fa1.w, b0, b1);
                }
            }
        }

        // S(j) + softmax + dual-stage P(j)
        {
            float c[2][2][4];
            compute_S_nt<2>(aq, sm + ((j & 1) ? KS1 : KS0), wn * 16, g, tig, c);
            unsigned wbits = mw[2 * j + (wn >> 1)];
            float* Pr = PROW(j);
            float* Pf = PFRG(j);
#pragma unroll
            for (int ms = 0; ms < 2; ++ms)
#pragma unroll
                for (int nt = 0; nt < 2; ++nt) {
                    int base = (wn & 1) * 16 + nt * 8 + 2 * tig;
                    float p0 = ((wbits >> base) & 1u) ? ex2f_(c[ms][nt][0]) * rri[2 * ms] : 0.f;
                    float p1 = ((wbits >> (base + 1)) & 1u) ? ex2f_(c[ms][nt][1]) * rri[2 * ms] : 0.f;
                    float p2 = ((wbits >> base) & 1u) ? ex2f_(c[ms][nt][2]) * rri[2 * ms + 1] : 0.f;
                    float p3 = ((wbits >> (base + 1)) & 1u) ? ex2f_(c[ms][nt][3]) * rri[2 * ms + 1] : 0.f;
                    unsigned u0 = cvt_tf32(p0), u1 = cvt_tf32(p1), u2 = cvt_tf32(p2), u3 = cvt_tf32(p3);
                    int lr = wm * 32 + ms * 16 + g, lc = wn * 16 + nt * 8 + 2 * tig;
                    *(uint2*)(Pr + lr * 68 + lc) = make_uint2(u0, u1);
                    *(uint2*)(Pr + (lr + 8) * 68 + lc) = make_uint2(u2, u3);
                    int kb = wn * 2 + nt;
                    float* fb = Pf + ((ms * 8 + kb) * 4 + tigf0) * 32 + g * 4 + fcomp;
                    *(uint2*)fb = make_uint2(u0, u2);
                    *(uint2*)(fb + 32) = make_uint2(u1, u3);
                }
        }
    }

    // ---- epilogue: consume P(31), V(31) ----
    CP_WAIT0();
    __syncthreads();
    {
        const float* Pr = PROW(31);
#pragma unroll
        for (int it = 0; it < 4; ++it) {
            int idx = tid + it * 512;
            int row = idx >> 4, c4 = (idx & 15) << 2;
            float4 pv = *(const float4*)(Pr + row * 68 + c4);
            *(float4*)(attg + (size_t)row * NSEQ + 31 * 64 + c4) = pv;
        }
        const float* Pf = PFRG(31);
        const float* Vs = VBUF(31);
#pragma unroll
        for (int kb = 0; kb < 8; ++kb) {
            uint4 fa0 = *(const uint4*)(Pf + ((0 * 8 + kb) * 4 + tig) * 32 + g * 4);
            uint4 fa1 = *(const uint4*)(Pf + ((1 * 8 + kb) * 4 + tig) * 32 + g * 4);
#pragma unroll
            for (int nt = 0; nt < 2; ++nt) {
                unsigned b0 = __float_as_uint(Vs[(kb * 8 + tig) * 72 + wn * 16 + nt * 8 + g]);
                unsigned b1 = __float_as_uint(Vs[(kb * 8 + tig + 4) * 72 + wn * 16 + nt * 8 + g]);
                mma_tf32(o[0][nt], fa0.x, fa0.y, fa0.z, fa0.w, b0, b1);
                mma_tf32(o[1][nt], fa1.x, fa1.y, fa1.z, fa1.w, b0, b1);
            }
        }
    }

    // ---- O store (already normalized) ----
#pragma unroll
    for (int ms = 0; ms < 2; ++ms)
#pragma unroll
        for (int nt = 0; nt < 2; ++nt) {
            int row = wm * 32 + ms * 16 + g;
            int col = wn * 16 + nt * 8 + 2 * tig;
            float* og0 = out + ((size_t)bh * NSEQ + i0 + row) * 64 + col;
            float* og1 = out + ((size_t)bh * NSEQ + i0 + row + 8) * 64 + col;
            *(float2*)og0 = make_float2(o[ms][nt][0], o[ms][nt][1]);
            *(float2*)og1 = make_float2(o[ms][nt][2], o[ms][nt][3]);
        }
#undef PROW
#undef PFRG
#undef VBUF
}

extern "C" void kernel_launch(void* const* d_in, const int* in_sizes, int n_in,
                              void* d_out, int out_size) {
    const float* q = (const float*)d_in[0];
    const float* k = (const float*)d_in[1];
    const float* v = (const float*)d_in[2];
    const int* mask = (const int*)d_in[3];
    float* out = (float*)d_out;

    const int smem_bytes = SMEMF * (int)sizeof(float);   // 209,664 B
    cudaFuncSetAttribute(lg14_kernel, cudaFuncAttributeMaxDynamicSharedMemorySize, smem_bytes);

    kv_cvt<<<KVELEMS / (512 * 4), 512>>>(k, v);
    dim3 grid(NSEQ / 128, 16);
    lg14_kernel<<<grid, 512, smem_bytes>>>(q, mask, out);
}

// round 15
// speedup vs baseline: 1.4642x; 1.4642x over previous
#include <cuda_runtime.h>
#include <cstdint>

#define NSEQ 2048
#define SCALEQ 0.18033688011112042f   // (1/sqrt(64)) * log2(e)

static const size_t ATT_OFF = 2097152;   // 16*2048*64

// smem float offsets
#define QP    0        // Q stage / P row buf 0: 128 x 68
#define P1R   8704     // P row buf 1: 128 x 68
#define KS0   17408    // pass B K: 64 x 68
#define KS1   21760
#define VS0   26112    // pass B V ring: 3 x (64 x 72), ends 39936
#define MSK   43520    // 64 u32
#define SLP   43584    // 4 x 128 partial row sums
#define RRI   44096    // 128
#define SMEMF 44224    // 176,896 B
// pass A mega-K buffers (256 x 68 each), aliasing pass-B-only regions:
#define KA0   8704     // = P1R + KS0 + KS1 (8704..26112)
#define KA1   26112    // = V ring + slack  (26112..43520)

#define KVELEMS (16 * 2048 * 64)
__device__ float g_kc[KVELEMS];   // K pre-converted to tf32 bits
__device__ float g_vc[KVELEMS];   // V pre-converted to tf32 bits

__device__ __forceinline__ uint32_t smem_u32(const void* p) {
    uint32_t a;
    asm("{ .reg .u64 t; cvta.to.shared.u64 t, %1; cvt.u32.u64 %0, t; }" : "=r"(a) : "l"(p));
    return a;
}
__device__ __forceinline__ float ex2f_(float x) {
    float y; asm("ex2.approx.ftz.f32 %0, %1;" : "=f"(y) : "f"(x)); return y;
}
__device__ __forceinline__ unsigned cvt_tf32(float x) {
    unsigned y; asm("cvt.rna.tf32.f32 %0, %1;" : "=r"(y) : "f"(x)); return y;
}
__device__ __forceinline__ void mma_tf32(float c[4],
                                         unsigned a0, unsigned a1, unsigned a2, unsigned a3,
                                         unsigned b0, unsigned b1) {
    asm volatile(
        "mma.sync.aligned.m16n8k8.row.col.f32.tf32.tf32.f32 "
        "{%0,%1,%2,%3}, {%4,%5,%6,%7}, {%8,%9}, {%0,%1,%2,%3};"
        : "+f"(c[0]), "+f"(c[1]), "+f"(c[2]), "+f"(c[3])
        : "r"(a0), "r"(a1), "r"(a2), "r"(a3), "r"(b0), "r"(b1));
}

__device__ __forceinline__ void cp16(uint32_t dst, const void* src) {
    asm volatile("cp.async.cg.shared.global [%0], [%1], 16;" :: "r"(dst), "l"(src) : "memory");
}
#define CP_COMMIT() asm volatile("cp.async.commit_group;" ::: "memory")
#define CP_WAIT0()  asm volatile("cp.async.wait_group 0;" ::: "memory")

// =============== Kernel 0: pre-convert K,V to tf32 bits ===============
__global__ void __launch_bounds__(512, 4)
kv_cvt(const float* __restrict__ k, const float* __restrict__ v) {
    int idx = (blockIdx.x * 512 + threadIdx.x) * 4;
    if (idx < KVELEMS) {
        float4 tk = *(const float4*)(k + idx);
        float4 tv = *(const float4*)(v + idx);
        uint4 uk, uv;
        uk.x = cvt_tf32(tk.x); uk.y = cvt_tf32(tk.y); uk.z = cvt_tf32(tk.z); uk.w = cvt_tf32(tk.w);
        uv.x = cvt_tf32(tv.x); uv.y = cvt_tf32(tv.y); uv.z = cvt_tf32(tv.z); uv.w = cvt_tf32(tv.w);
        *(uint4*)(g_kc + idx) = uk;
        *(uint4*)(g_vc + idx) = uv;
    }
}

// 64x64 fp32 tile -> smem (512 thr x 2 chunks of 16B)
__device__ __forceinline__ void issue_tile64(uint32_t buf, const float* src, int tid, int strideB) {
#pragma unroll
    for (int it = 0; it < 2; ++it) {
        int idx = tid + it * 512;
        int row = idx >> 4, c16 = (idx & 15) << 4;
        cp16(buf + row * strideB + c16, (const char*)src + row * 256 + c16);
    }
}
// 128x64 fp32 tile -> smem (512 thr x 4 chunks)
__device__ __forceinline__ void issue_tile128(uint32_t buf, const float* src, int tid, int strideB) {
#pragma unroll
    for (int it = 0; it < 4; ++it) {
        int idx = tid + it * 512;
        int row = idx >> 4, c16 = (idx & 15) << 4;
        cp16(buf + row * strideB + c16, (const char*)src + row * 256 + c16);
    }
}
// 256x64 fp32 tile -> smem (two 128-row halves)
__device__ __forceinline__ void issue_tile256(uint32_t buf, const float* src, int tid) {
    issue_tile128(buf, src, tid, 272);
    issue_tile128(buf + 8704 * 4, src + 128 * 64, tid, 272);
}

// S warp-tile: rows wm*32..+31, keys keybase + nt*8 (NT n-subtiles); K already tf32 bits
template <int NT>
__device__ __forceinline__ void compute_S_nt(const unsigned aq[8][2][4], const float* __restrict__ Ks,
                                             int keybase, int g, int tig, float c[2][NT][4]) {
#pragma unroll
    for (int ms = 0; ms < 2; ++ms)
#pragma unroll
        for (int nt = 0; nt < NT; ++nt)
#pragma unroll
            for (int e = 0; e < 4; ++e) c[ms][nt][e] = 0.f;
#pragma unroll
    for (int ks = 0; ks < 8; ++ks) {
#pragma unroll
        for (int nt = 0; nt < NT; ++nt) {
            const float* kr = Ks + (keybase + nt * 8 + g) * 68 + ks * 8;
            unsigned b0 = __float_as_uint(kr[tig]);
            unsigned b1 = __float_as_uint(kr[tig + 4]);
            mma_tf32(c[0][nt], aq[ks][0][0], aq[ks][0][1], aq[ks][0][2], aq[ks][0][3], b0, b1);
            mma_tf32(c[1][nt], aq[ks][1][0], aq[ks][1][1], aq[ks][1][2], aq[ks][1][3], b0, b1);
        }
    }
}

__global__ void __launch_bounds__(512, 1)
lg15_kernel(const float* __restrict__ q, const int* __restrict__ mask,
            float* __restrict__ out) {
    extern __shared__ float sm[];
    const uint32_t sbu = smem_u32(sm);
    const int tid = threadIdx.x;
    const int w = tid >> 5, lane = tid & 31;
    const int wm = w & 3, wn = w >> 2;           // 4 row groups x 4 key groups
    const int g = lane >> 2, tig = lane & 3;

    const int bh = blockIdx.y, b = bh >> 2;      // H = 4
    const int i0 = blockIdx.x * 128;
    const float* qg = q + ((size_t)bh * NSEQ + i0) * 64;
    const float* kg = g_kc + (size_t)bh * NSEQ * 64;
    const float* vg = g_vc + (size_t)bh * NSEQ * 64;
    const int* mg = mask + (size_t)b * NSEQ;
    float* attg = out + ATT_OFF + ((size_t)bh * NSEQ + i0) * NSEQ;
    const unsigned* mw = (const unsigned*)(sm + MSK);

    // ---- prologue: Q (scaled, tf32) into QP; mask bitwords; K mega-tile 0 (256 keys) ----
#pragma unroll
    for (int it = 0; it < 4; ++it) {
        int idx = tid + it * 512;
        int r = idx >> 4, c4 = (idx & 15) << 2;
        float4 t = *(const float4*)(qg + r * 64 + c4);
        uint4 u;
        u.x = cvt_tf32(t.x * SCALEQ); u.y = cvt_tf32(t.y * SCALEQ);
        u.z = cvt_tf32(t.z * SCALEQ); u.w = cvt_tf32(t.w * SCALEQ);
        *(uint4*)(sm + QP + r * 68 + c4) = u;
    }
    if (tid < 64) {
        unsigned bits = 0;
#pragma unroll 8
        for (int r = 0; r < 32; ++r) bits |= (mg[tid * 32 + r] != 0 ? 1u : 0u) << r;
        ((unsigned*)(sm + MSK))[tid] = bits;
    }
    issue_tile256(sbu + KA0 * 4, kg, tid);
    CP_COMMIT();
    __syncthreads();

    // Q A-fragments register-resident for both passes
    unsigned aq[8][2][4];
#pragma unroll
    for (int ks = 0; ks < 8; ++ks)
#pragma unroll
        for (int ms = 0; ms < 2; ++ms) {
            const float* qr = sm + QP + (wm * 32 + ms * 16 + g) * 68 + ks * 8;
            aq[ks][ms][0] = __float_as_uint(qr[tig]);
            aq[ks][ms][1] = __float_as_uint(qr[8 * 68 + tig]);
            aq[ks][ms][2] = __float_as_uint(qr[tig + 4]);
            aq[ks][ms][3] = __float_as_uint(qr[8 * 68 + tig + 4]);
        }

    // =================== Pass A: row sums, 256-key mega-tiles (8 barrier iters) ===================
    float l[4] = {0.f, 0.f, 0.f, 0.f};   // slot s: row wm*32 + (s>>1)*16 + g + (s&1)*8
    for (int j = 0; j < 8; ++j) {
        CP_WAIT0();
        __syncthreads();
        if (j < 7) {
            issue_tile256(sbu + (((j + 1) & 1) ? KA1 : KA0) * 4, kg + (size_t)(j + 1) * 256 * 64, tid);
            CP_COMMIT();
        }
#pragma unroll
        for (int h = 0; h < 2; ++h) {
            const float* Ks = sm + ((j & 1) ? KA1 : KA0) + h * 8704;
            float c[2][4][4];
            compute_S_nt<4>(aq, Ks, wn * 32, g, tig, c);

            unsigned wbits = mw[8 * j + 4 * h + wn];
#pragma unroll
            for (int ms = 0; ms < 2; ++ms)
#pragma unroll
                for (int nt = 0; nt < 4; ++nt) {
                    int base = nt * 8 + 2 * tig;
                    float e0 = ((wbits >> base) & 1u) ? ex2f_(c[ms][nt][0]) : 0.f;
                    float e1 = ((wbits >> (base + 1)) & 1u) ? ex2f_(c[ms][nt][1]) : 0.f;
                    float e2 = ((wbits >> base) & 1u) ? ex2f_(c[ms][nt][2]) : 0.f;
                    float e3 = ((wbits >> (base + 1)) & 1u) ? ex2f_(c[ms][nt][3]) : 0.f;
                    l[ms * 2] += e0 + e1;
                    l[ms * 2 + 1] += e2 + e3;
                }
        }
    }

    // K(0) prefetch safe now (KS0 inside KA0; last mega-iter read KA1)
    issue_tile64(sbu + KS0 * 4, kg, tid, 272);
    CP_COMMIT();

    // reduce l: tig lanes, then wn groups via smem
#pragma unroll
    for (int s = 0; s < 4; ++s) {
        l[s] += __shfl_xor_sync(0xffffffffu, l[s], 1);
        l[s] += __shfl_xor_sync(0xffffffffu, l[s], 2);
    }
    if (tig == 0) {
#pragma unroll
        for (int s = 0; s < 4; ++s) {
            int row = wm * 32 + (s >> 1) * 16 + g + (s & 1) * 8;
            sm[SLP + wn * 128 + row] = l[s];
        }
    }
    __syncthreads();   // all KA1 reads done -> V ring (aliasing it) now writable
    issue_tile64(sbu + VS0 * 4, vg, tid, 288);
    CP_COMMIT();
    if (tid < 128) {
        float lt = sm[SLP + tid] + sm[SLP + 128 + tid] + sm[SLP + 256 + tid] + sm[SLP + 384 + tid];
        sm[RRI + tid] = 1.0f / lt;
    }
    __syncthreads();

    float rri[4];
#pragma unroll
    for (int s = 0; s < 4; ++s)
        rri[s] = sm[RRI + wm * 32 + (s >> 1) * 16 + g + (s & 1) * 8];

    // =================== Pass B: pipelined — iter j consumes P(j-1), produces P(j) ===================
    float o[2][2][4];
#pragma unroll
    for (int ms = 0; ms < 2; ++ms)
#pragma unroll
        for (int nt = 0; nt < 2; ++nt)
#pragma unroll
            for (int e = 0; e < 4; ++e) o[ms][nt][e] = 0.f;

#define PBUF(jj) (sm + (((jj) & 1) ? P1R : QP))
#define VBUF(jj) (sm + VS0 + ((jj) % 3) * 4608)

    // ---- prologue iteration (j = 0): S(0), softmax, stage P(0) ----
    {
        CP_WAIT0();
        __syncthreads();   // K(0), V(0) arrived
        issue_tile64(sbu + KS1 * 4, kg + (size_t)64 * 64, tid, 272);
        issue_tile64(sbu + (VS0 + 4608) * 4, vg + (size_t)64 * 64, tid, 288);
        CP_COMMIT();

        float c[2][2][4];
        compute_S_nt<2>(aq, sm + KS0, wn * 16, g, tig, c);
        unsigned wbits = mw[wn >> 1];
        float* Pb = PBUF(0);
#pragma unroll
        for (int ms = 0; ms < 2; ++ms)
#pragma unroll
            for (int nt = 0; nt < 2; ++nt) {
                int base = (wn & 1) * 16 + nt * 8 + 2 * tig;
                float p0 = ((wbits >> base) & 1u) ? ex2f_(c[ms][nt][0]) * rri[2 * ms] : 0.f;
                float p1 = ((wbits >> (base + 1)) & 1u) ? ex2f_(c[ms][nt][1]) * rri[2 * ms] : 0.f;
                float p2 = ((wbits >> base) & 1u) ? ex2f_(c[ms][nt][2]) * rri[2 * ms + 1] : 0.f;
                float p3 = ((wbits >> (base + 1)) & 1u) ? ex2f_(c[ms][nt][3]) * rri[2 * ms + 1] : 0.f;
                int lr = wm * 32 + ms * 16 + g, lc = wn * 16 + nt * 8 + 2 * tig;
                *(uint2*)(Pb + lr * 68 + lc) = make_uint2(cvt_tf32(p0), cvt_tf32(p1));
                *(uint2*)(Pb + (lr + 8) * 68 + lc) = make_uint2(cvt_tf32(p2), cvt_tf32(p3));
            }
    }

    // ---- main loop: j = 1..31 ----
    for (int j = 1; j < 32; ++j) {
        CP_WAIT0();
        __syncthreads();   // K/V(j) arrived; P(j-1) visible; P buf (j&1) free

        if (j < 31) {
            issue_tile64(sbu + (((j + 1) & 1) ? KS1 : KS0) * 4, kg + (size_t)(j + 1) * 64 * 64, tid, 272);
            issue_tile64(sbu + (VS0 + ((j + 1) % 3) * 4608) * 4, vg + (size_t)(j + 1) * 64 * 64, tid, 288);
            CP_COMMIT();
        }

        const float* Pp = PBUF(j - 1);

        // attention store for tile j-1 (coalesced 256B row segments)
#pragma unroll
        for (int it = 0; it < 4; ++it) {
            int idx = tid + it * 512;
            int row = idx >> 4, c4 = (idx & 15) << 2;
            float4 pv = *(const float4*)(Pp + row * 68 + c4);
            *(float4*)(attg + (size_t)row * NSEQ + (j - 1) * 64 + c4) = pv;
        }

        // PV(j-1): this warp, all 64 keys x its 16 d-columns
        {
            const float* Vs = VBUF(j - 1);
#pragma unroll
            for (int kb = 0; kb < 8; ++kb) {
                unsigned a[2][4];
#pragma unroll
                for (int ms = 0; ms < 2; ++ms) {
                    const float* pr = Pp + (wm * 32 + ms * 16 + g) * 68 + kb * 8;
                    a[ms][0] = __float_as_uint(pr[tig]);
                    a[ms][1] = __float_as_uint(pr[8 * 68 + tig]);
                    a[ms][2] = __float_as_uint(pr[tig + 4]);
                    a[ms][3] = __float_as_uint(pr[8 * 68 + tig + 4]);
                }
#pragma unroll
                for (int nt = 0; nt < 2; ++nt) {
                    unsigned b0 = __float_as_uint(Vs[(kb * 8 + tig) * 72 + wn * 16 + nt * 8 + g]);
                    unsigned b1 = __float_as_uint(Vs[(kb * 8 + tig + 4) * 72 + wn * 16 + nt * 8 + g]);
                    mma_tf32(o[0][nt], a[0][0], a[0][1], a[0][2], a[0][3], b0, b1);
                    mma_tf32(o[1][nt], a[1][0], a[1][1], a[1][2], a[1][3], b0, b1);
                }
            }
        }

        // S(j) + softmax + stage P(j)
        {
            float c[2][2][4];
            compute_S_nt<2>(aq, sm + ((j & 1) ? KS1 : KS0), wn * 16, g, tig, c);
            unsigned wbits = mw[2 * j + (wn >> 1)];
            float* Pb = PBUF(j);
#pragma unroll
            for (int ms = 0; ms < 2; ++ms)
#pragma unroll
                for (int nt = 0; nt < 2; ++nt) {
                    int base = (wn & 1) * 16 + nt * 8 + 2 * tig;
                    float p0 = ((wbits >> base) & 1u) ? ex2f_(c[ms][nt][0]) * rri[2 * ms] : 0.f;
                    float p1 = ((wbits >> (base + 1)) & 1u) ? ex2f_(c[ms][nt][1]) * rri[2 * ms] : 0.f;
                    float p2 = ((wbits >> base) & 1u) ? ex2f_(c[ms][nt][2]) * rri[2 * ms + 1] : 0.f;
                    float p3 = ((wbits >> (base + 1)) & 1u) ? ex2f_(c[ms][nt][3]) * rri[2 * ms + 1] : 0.f;
                    int lr = wm * 32 + ms * 16 + g, lc = wn * 16 + nt * 8 + 2 * tig;
                    *(uint2*)(Pb + lr * 68 + lc) = make_uint2(cvt_tf32(p0), cvt_tf32(p1));
                    *(uint2*)(Pb + (lr + 8) * 68 + lc) = make_uint2(cvt_tf32(p2), cvt_tf32(p3));
                }
        }
    }

    // ---- epilogue: consume P(31) ----
    __syncthreads();
    {
        const float* Pp = PBUF(31);
#pragma unroll
        for (int it = 0; it < 4; ++it) {
            int idx = tid + it * 512;
            int row = idx >> 4, c4 = (idx & 15) << 2;
            float4 pv = *(const float4*)(Pp + row * 68 + c4);
            *(float4*)(attg + (size_t)row * NSEQ + 31 * 64 + c4) = pv;
        }
        const float* Vs = VBUF(31);
#pragma unroll
        for (int kb = 0; kb < 8; ++kb) {
            unsigned a[2][4];
#pragma unroll
            for (int ms = 0; ms < 2; ++ms) {
                const float* pr = Pp + (wm * 32 + ms * 16 + g) * 68 + kb * 8;
                a[ms][0] = __float_as_uint(pr[tig]);
                a[ms][1] = __float_as_uint(pr[8 * 68 + tig]);
                a[ms][2] = __float_as_uint(pr[tig + 4]);
                a[ms][3] = __float_as_uint(pr[8 * 68 + tig + 4]);
            }
#pragma unroll
            for (int nt = 0; nt < 2; ++nt) {
                unsigned b0 = __float_as_uint(Vs[(kb * 8 + tig) * 72 + wn * 16 + nt * 8 + g]);
                unsigned b1 = __float_as_uint(Vs[(kb * 8 + tig + 4) * 72 + wn * 16 + nt * 8 + g]);
                mma_tf32(o[0][nt], a[0][0], a[0][1], a[0][2], a[0][3], b0, b1);
                mma_tf32(o[1][nt], a[1][0], a[1][1], a[1][2], a[1][3], b0, b1);
            }
        }
    }

    // ---- O store (already normalized) ----
#pragma unroll
    for (int ms = 0; ms < 2; ++ms)
#pragma unroll
        for (int nt = 0; nt < 2; ++nt) {
            int row = wm * 32 + ms * 16 + g;
            int col = wn * 16 + nt * 8 + 2 * tig;
            float* og0 = out + ((size_t)bh * NSEQ + i0 + row) * 64 + col;
            float* og1 = out + ((size_t)bh * NSEQ + i0 + row + 8) * 64 + col;
            *(float2*)og0 = make_float2(o[ms][nt][0], o[ms][nt][1]);
            *(float2*)og1 = make_float2(o[ms][nt][2], o[ms][nt][3]);
        }
#undef PBUF
#undef VBUF
}

extern "C" void kernel_launch(void* const* d_in, const int* in_sizes, int n_in,
                              void* d_out, int out_size) {
    const float* q = (const float*)d_in[0];
    const float* k = (const float*)d_in[1];
    const float* v = (const float*)d_in[2];
    const int* mask = (const int*)d_in[3];
    float* out = (float*)d_out;

    const int smem_bytes = SMEMF * (int)sizeof(float);   // 176,896 B
    cudaFuncSetAttribute(lg15_kernel, cudaFuncAttributeMaxDynamicSharedMemorySize, smem_bytes);

    kv_cvt<<<KVELEMS / (512 * 4), 512>>>(k, v);
    dim3 grid(NSEQ / 128, 16);
    lg15_kernel<<<grid, 512, smem_bytes>>>(q, mask, out);
}

// round 16
// speedup vs baseline: 2.0821x; 1.4221x over previous
#include <cuda_runtime.h>
#include <cuda_fp16.h>
#include <cstdint>

#define NSEQ 2048
#define SCALEQ 0.18033688011112042f   // (1/sqrt(64)) * log2(e)
#define PW 36                          // smem row stride in 4B words (64 fp16 + 8 pad)

static const size_t ATT_OFF = 2097152;   // 16*2048*64

// smem WORD offsets
#define P0W   0        // Q stage / P buf0: 128 x PW
#define P1W   4608     // P buf1
#define KS0W  9216     // pass B K: 64 x PW
#define KS1W  11520
#define VT0W  13824    // Vt ring x3, stride 2304
#define MSKW  20736    // 64 u32
#define SLPW  20800    // 4 x 128 f32
#define RRIW  21312    // 128 f32
#define SMEMW 21440    // 85,760 B
// pass A mega-K buffers (128 rows x PW), aliasing pass-B-only regions:
#define KA0W  9216     // = KS0+KS1
#define KA1W  13824    // = VT0+VT1

#define KVELEMS (16 * 2048 * 64)
__device__ __half g_kh[KVELEMS];   // K as fp16, [bh][key][d]
__device__ __half g_vt[KVELEMS];   // V as fp16 TRANSPOSED, [bh][d][key]

__device__ __forceinline__ uint32_t smem_u32(const void* p) {
    uint32_t a;
    asm("{ .reg .u64 t; cvta.to.shared.u64 t, %1; cvt.u32.u64 %0, t; }" : "=r"(a) : "l"(p));
    return a;
}
__device__ __forceinline__ float ex2f_(float x) {
    float y; asm("ex2.approx.ftz.f32 %0, %1;" : "=f"(y) : "f"(x)); return y;
}
__device__ __forceinline__ unsigned h2bits(__half2 h) {
    return *reinterpret_cast<unsigned*>(&h);
}
__device__ __forceinline__ void mma_f16(float c[4], const unsigned a[4], unsigned b0, unsigned b1) {
    asm volatile(
        "mma.sync.aligned.m16n8k16.row.col.f32.f16.f16.f32 "
        "{%0,%1,%2,%3}, {%4,%5,%6,%7}, {%8,%9}, {%0,%1,%2,%3};"
        : "+f"(c[0]), "+f"(c[1]), "+f"(c[2]), "+f"(c[3])
        : "r"(a[0]), "r"(a[1]), "r"(a[2]), "r"(a[3]), "r"(b0), "r"(b1));
}

__device__ __forceinline__ void cp16(uint32_t dst, const void* src) {
    asm volatile("cp.async.cg.shared.global [%0], [%1], 16;" :: "r"(dst), "l"(src) : "memory");
}
#define CP_COMMIT() asm volatile("cp.async.commit_group;" ::: "memory")
#define CP_WAIT0()  asm volatile("cp.async.wait_group 0;" ::: "memory")

// =============== Kernel 0a: K fp32 -> fp16 ===============
__global__ void __launch_bounds__(512, 4)
k_cvt(const float* __restrict__ k) {
    int i4 = blockIdx.x * 512 + threadIdx.x;          // float4 index
    float4 t = ((const float4*)k)[i4];
    __half2 h0 = __floats2half2_rn(t.x, t.y);
    __half2 h1 = __floats2half2_rn(t.z, t.w);
    ((uint2*)g_kh)[i4] = make_uint2(h2bits(h0), h2bits(h1));
}

// =============== Kernel 0b: V fp32 -> fp16 transposed [bh][d][key] ===============
__global__ void __launch_bounds__(256, 4)
v_tr(const float* __restrict__ v) {
    __shared__ float ts[64][65];
    int bh = blockIdx.y, jt = blockIdx.x;
    const float* src = v + ((size_t)bh * NSEQ + jt * 64) * 64;
    int tid = threadIdx.x;
#pragma unroll
    for (int it = 0; it < 4; ++it) {
        int idx = tid + it * 256;
        int r = idx >> 4, c4 = (idx & 15) << 2;
        float4 t = *(const float4*)(src + r * 64 + c4);
        ts[r][c4] = t.x; ts[r][c4 + 1] = t.y; ts[r][c4 + 2] = t.z; ts[r][c4 + 3] = t.w;
    }
    __syncthreads();
    int d = tid >> 2, kg = (tid & 3) * 16;
    __half* dst = g_vt + (size_t)bh * 64 * NSEQ + (size_t)d * NSEQ + jt * 64 + kg;
#pragma unroll
    for (int kk = 0; kk < 16; kk += 2) {
        __half2 h = __floats2half2_rn(ts[kg + kk][d], ts[kg + kk + 1][d]);
        *(__half2*)(dst + kk) = h;
    }
}

// fp16 tile rows -> smem (8 x 16B chunks per 64-row tile-row; dst stride 144B)
__device__ __forceinline__ void issue_rows64(uint32_t dstB, const __half* src, int srcStrideH, int tid) {
    int row = tid >> 3, ch = tid & 7;
    cp16(dstB + row * 144 + ch * 16, (const char*)src + (size_t)row * srcStrideH * 2 + ch * 16);
}
__device__ __forceinline__ void issue_rows128(uint32_t dstB, const __half* src, int tid) {
#pragma unroll
    for (int it = 0; it < 2; ++it) {
        int idx = tid + it * 512;
        int row = idx >> 3, ch = idx & 7;
        cp16(dstB + row * 144 + ch * 16, (const char*)src + (size_t)row * 128 + ch * 16);
    }
}

// S warp-tile: rows wm*32..+31, keys keybase + nt*8 (NT n-subtiles); fp16 K in smem words
template <int NT>
__device__ __forceinline__ void compute_S_h(const unsigned aq[4][2][4], const unsigned* __restrict__ Ks,
                                            int keybase, int g, int tig, float c[2][NT][4]) {
#pragma unroll
    for (int ms = 0; ms < 2; ++ms)
#pragma unroll
        for (int nt = 0; nt < NT; ++nt)
#pragma unroll
            for (int e = 0; e < 4; ++e) c[ms][nt][e] = 0.f;
#pragma unroll
    for (int ks = 0; ks < 4; ++ks) {
#pragma unroll
        for (int nt = 0; nt < NT; ++nt) {
            const unsigned* kr = Ks + (keybase + nt * 8 + g) * PW + ks * 8;
            unsigned b0 = kr[tig];
            unsigned b1 = kr[tig + 4];
            mma_f16(c[0][nt], aq[ks][0], b0, b1);
            mma_f16(c[1][nt], aq[ks][1], b0, b1);
        }
    }
}

__global__ void __launch_bounds__(512, 1)
lg16_kernel(const float* __restrict__ q, const int* __restrict__ mask,
            float* __restrict__ out) {
    extern __shared__ float sm[];
    unsigned* smw = (unsigned*)sm;
    const uint32_t sbu = smem_u32(sm);
    const int tid = threadIdx.x;
    const int w = tid >> 5, lane = tid & 31;
    const int wm = w & 3, wn = w >> 2;           // 4 row groups x 4 key groups
    const int g = lane >> 2, tig = lane & 3;

    const int bh = blockIdx.y, b = bh >> 2;      // H = 4
    const int i0 = blockIdx.x * 128;
    const float* qg = q + ((size_t)bh * NSEQ + i0) * 64;
    const __half* kg = g_kh + (size_t)bh * NSEQ * 64;
    const __half* vtg = g_vt + (size_t)bh * 64 * NSEQ;
    const int* mg = mask + (size_t)b * NSEQ;
    float* attg = out + ATT_OFF + ((size_t)bh * NSEQ + i0) * NSEQ;
    const unsigned* mw = smw + MSKW;

    // ---- prologue: Q (scaled, fp16) into P0 region; mask bitwords; K mega-tile 0 ----
#pragma unroll
    for (int it = 0; it < 4; ++it) {
        int idx = tid + it * 512;
        int r = idx >> 4, c4 = (idx & 15) << 2;
        float4 t = *(const float4*)(qg + r * 64 + c4);
        __half2 h0 = __floats2half2_rn(t.x * SCALEQ, t.y * SCALEQ);
        __half2 h1 = __floats2half2_rn(t.z * SCALEQ, t.w * SCALEQ);
        *(uint2*)(smw + P0W + r * PW + (c4 >> 1)) = make_uint2(h2bits(h0), h2bits(h1));
    }
    if (tid < 64) {
        unsigned bits = 0;
#pragma unroll 8
        for (int r = 0; r < 32; ++r) bits |= (mg[tid * 32 + r] != 0 ? 1u : 0u) << r;
        smw[MSKW + tid] = bits;
    }
    issue_rows128(sbu + KA0W * 4, kg, tid);
    CP_COMMIT();
    __syncthreads();

    // Q A-fragments register-resident (32 regs)
    unsigned aq[4][2][4];
#pragma unroll
    for (int ks = 0; ks < 4; ++ks)
#pragma unroll
        for (int ms = 0; ms < 2; ++ms) {
            const unsigned* qr = smw + P0W + (wm * 32 + ms * 16 + g) * PW + ks * 8;
            aq[ks][ms][0] = qr[tig];
            aq[ks][ms][1] = qr[8 * PW + tig];
            aq[ks][ms][2] = qr[tig + 4];
            aq[ks][ms][3] = qr[8 * PW + tig + 4];
        }

    // =================== Pass A: row sums, 128-key mega-tiles (16 iters) ===================
    float l[4] = {0.f, 0.f, 0.f, 0.f};   // slot s: row wm*32 + (s>>1)*16 + g + (s&1)*8
    for (int j = 0; j < 16; ++j) {
        CP_WAIT0();
        __syncthreads();
        if (j < 15) {
            issue_rows128(sbu + (((j + 1) & 1) ? KA1W : KA0W) * 4, kg + (size_t)(j + 1) * 128 * 64, tid);
            CP_COMMIT();
        }
        float c[2][4][4];
        compute_S_h<4>(aq, smw + ((j & 1) ? KA1W : KA0W), wn * 32, g, tig, c);

        unsigned wbits = mw[4 * j + wn];
#pragma unroll
        for (int ms = 0; ms < 2; ++ms)
#pragma unroll
            for (int nt = 0; nt < 4; ++nt) {
                int base = nt * 8 + 2 * tig;
                float e0 = ((wbits >> base) & 1u) ? ex2f_(c[ms][nt][0]) : 0.f;
                float e1 = ((wbits >> (base + 1)) & 1u) ? ex2f_(c[ms][nt][1]) : 0.f;
                float e2 = ((wbits >> base) & 1u) ? ex2f_(c[ms][nt][2]) : 0.f;
                float e3 = ((wbits >> (base + 1)) & 1u) ? ex2f_(c[ms][nt][3]) : 0.f;
                l[ms * 2] += e0 + e1;
                l[ms * 2 + 1] += e2 + e3;
            }
    }

    // K(0) prefetch (KS0 inside KA0; last mega-iter j=15 read KA1)
    issue_rows64(sbu + KS0W * 4, kg, 64, tid);
    CP_COMMIT();

    // reduce l: tig lanes, then wn groups via smem
#pragma unroll
    for (int s = 0; s < 4; ++s) {
        l[s] += __shfl_xor_sync(0xffffffffu, l[s], 1);
        l[s] += __shfl_xor_sync(0xffffffffu, l[s], 2);
    }
    if (tig == 0) {
#pragma unroll
        for (int s = 0; s < 4; ++s) {
            int row = wm * 32 + (s >> 1) * 16 + g + (s & 1) * 8;
            sm[SLPW + wn * 128 + row] = l[s];
        }
    }
    __syncthreads();   // all KA1 reads done -> Vt ring (aliasing it) writable
    issue_rows64(sbu + VT0W * 4, vtg, NSEQ, tid);
    CP_COMMIT();
    if (tid < 128) {
        float lt = sm[SLPW + tid] + sm[SLPW + 128 + tid] + sm[SLPW + 256 + tid] + sm[SLPW + 384 + tid];
        sm[RRIW + tid] = 1.0f / lt;
    }
    __syncthreads();

    float rri[4];
#pragma unroll
    for (int s = 0; s < 4; ++s)
        rri[s] = sm[RRIW + wm * 32 + (s >> 1) * 16 + g + (s & 1) * 8];

    // =================== Pass B: pipelined — iter j consumes P(j-1), produces P(j) ===================
    float o[2][2][4];
#pragma unroll
    for (int ms = 0; ms < 2; ++ms)
#pragma unroll
        for (int nt = 0; nt < 2; ++nt)
#pragma unroll
            for (int e = 0; e < 4; ++e) o[ms][nt][e] = 0.f;

#define PBUF(jj) (smw + (((jj) & 1) ? P1W : P0W))
#define VTBUF(jj) (smw + VT0W + ((jj) % 3) * 2304)

    // ---- prologue iteration (j = 0): S(0), softmax, stage P(0) fp16 ----
    {
        CP_WAIT0();
        __syncthreads();   // K(0), Vt(0) arrived
        issue_rows64(sbu + KS1W * 4, kg + (size_t)64 * 64, 64, tid);
        issue_rows64(sbu + (VT0W + 2304) * 4, vtg + 64, NSEQ, tid);
        CP_COMMIT();

        float c[2][2][4];
        compute_S_h<2>(aq, smw + KS0W, wn * 16, g, tig, c);
        unsigned wbits = mw[wn >> 1];
        unsigned* Pb = PBUF(0);
#pragma unroll
        for (int ms = 0; ms < 2; ++ms)
#pragma unroll
            for (int nt = 0; nt < 2; ++nt) {
                int base = (wn & 1) * 16 + nt * 8 + 2 * tig;
                float p0 = ((wbits >> base) & 1u) ? ex2f_(c[ms][nt][0]) * rri[2 * ms] : 0.f;
                float p1 = ((wbits >> (base + 1)) & 1u) ? ex2f_(c[ms][nt][1]) * rri[2 * ms] : 0.f;
                float p2 = ((wbits >> base) & 1u) ? ex2f_(c[ms][nt][2]) * rri[2 * ms + 1] : 0.f;
                float p3 = ((wbits >> (base + 1)) & 1u) ? ex2f_(c[ms][nt][3]) * rri[2 * ms + 1] : 0.f;
                int wi = (wm * 32 + ms * 16 + g) * PW + 8 * wn + 4 * nt + tig;
                Pb[wi] = h2bits(__floats2half2_rn(p0, p1));
                Pb[wi + 8 * PW] = h2bits(__floats2half2_rn(p2, p3));
            }
    }

    // ---- main loop: j = 1..31 ----
    for (int j = 1; j < 32; ++j) {
        CP_WAIT0();
        __syncthreads();   // K/Vt(j) arrived; P(j-1) visible; P buf (j&1) free

        if (j < 31) {
            issue_rows64(sbu + (((j + 1) & 1) ? KS1W : KS0W) * 4, kg + (size_t)(j + 1) * 64 * 64, 64, tid);
            issue_rows64(sbu + (VT0W + ((j + 1) % 3) * 2304) * 4, vtg + (j + 1) * 64, NSEQ, tid);
            CP_COMMIT();
        }

        const unsigned* Pp = PBUF(j - 1);

        // attention store for tile j-1: fp16 -> fp32, coalesced 256B row segments
#pragma unroll
        for (int it = 0; it < 2; ++it) {
            int idx = tid + it * 512;
            int row = idx >> 3, grp = idx & 7;
            uint4 wv = *(const uint4*)(Pp + row * PW + grp * 4);
            float2 f0 = __half22float2(*(__half2*)&wv.x);
            float2 f1 = __half22float2(*(__half2*)&wv.y);
            float2 f2 = __half22float2(*(__half2*)&wv.z);
            float2 f3 = __half22float2(*(__half2*)&wv.w);
            float* ab = attg + (size_t)row * NSEQ + (j - 1) * 64 + grp * 8;
            *(float4*)ab = make_float4(f0.x, f0.y, f1.x, f1.y);
            *(float4*)(ab + 4) = make_float4(f2.x, f2.y, f3.x, f3.y);
        }

        // PV(j-1): fp16 mma, A from P tile, B from Vt tile
        {
            const unsigned* Vt = VTBUF(j - 1);
#pragma unroll
            for (int kb = 0; kb < 4; ++kb) {
                unsigned a[2][4];
#pragma unroll
                for (int ms = 0; ms < 2; ++ms) {
                    const unsigned* pr = Pp + (wm * 32 + ms * 16 + g) * PW + kb * 8;
                    a[ms][0] = pr[tig];
                    a[ms][1] = pr[8 * PW + tig];
                    a[ms][2] = pr[tig + 4];
                    a[ms][3] = pr[8 * PW + tig + 4];
                }
#pragma unroll
                for (int nt = 0; nt < 2; ++nt) {
                    const unsigned* vr = Vt + (wn * 16 + nt * 8 + g) * PW + kb * 8;
                    unsigned b0 = vr[tig];
                    unsigned b1 = vr[tig + 4];
                    mma_f16(o[0][nt], a[0], b0, b1);
                    mma_f16(o[1][nt], a[1], b0, b1);
                }
            }
        }

        // S(j) + softmax + stage P(j) fp16
        {
            float c[2][2][4];
            compute_S_h<2>(aq, smw + ((j & 1) ? KS1W : KS0W), wn * 16, g, tig, c);
            unsigned wbits = mw[2 * j + (wn >> 1)];
            unsigned* Pb = PBUF(j);
#pragma unroll
            for (int ms = 0; ms < 2; ++ms)
#pragma unroll
                for (int nt = 0; nt < 2; ++nt) {
                    int base = (wn & 1) * 16 + nt * 8 + 2 * tig;
                    float p0 = ((wbits >> base) & 1u) ? ex2f_(c[ms][nt][0]) * rri[2 * ms] : 0.f;
                    float p1 = ((wbits >> (base + 1)) & 1u) ? ex2f_(c[ms][nt][1]) * rri[2 * ms] : 0.f;
                    float p2 = ((wbits >> base) & 1u) ? ex2f_(c[ms][nt][2]) * rri[2 * ms + 1] : 0.f;
                    float p3 = ((wbits >> (base + 1)) & 1u) ? ex2f_(c[ms][nt][3]) * rri[2 * ms + 1] : 0.f;
                    int wi = (wm * 32 + ms * 16 + g) * PW + 8 * wn + 4 * nt + tig;
                    Pb[wi] = h2bits(__floats2half2_rn(p0, p1));
                    Pb[wi + 8 * PW] = h2bits(__floats2half2_rn(p2, p3));
                }
        }
    }

    // ---- epilogue: consume P(31) ----
    __syncthreads();
    {
        const unsigned* Pp = PBUF(31);
#pragma unroll
        for (int it = 0; it < 2; ++it) {
            int idx = tid + it * 512;
            int row = idx >> 3, grp = idx & 7;
            uint4 wv = *(const uint4*)(Pp + row * PW + grp * 4);
            float2 f0 = __half22float2(*(__half2*)&wv.x);
            float2 f1 = __half22float2(*(__half2*)&wv.y);
            float2 f2 = __half22float2(*(__half2*)&wv.z);
            float2 f3 = __half22float2(*(__half2*)&wv.w);
            float* ab = attg + (size_t)row * NSEQ + 31 * 64 + grp * 8;
            *(float4*)ab = make_float4(f0.x, f0.y, f1.x, f1.y);
            *(float4*)(ab + 4) = make_float4(f2.x, f2.y, f3.x, f3.y);
        }
        const unsigned* Vt = VTBUF(31);
#pragma unroll
        for (int kb = 0; kb < 4; ++kb) {
            unsigned a[2][4];
#pragma unroll
            for (int ms = 0; ms < 2; ++ms) {
                const unsigned* pr = Pp + (wm * 32 + ms * 16 + g) * PW + kb * 8;
                a[ms][0] = pr[tig];
                a[ms][1] = pr[8 * PW + tig];
                a[ms][2] = pr[tig + 4];
                a[ms][3] = pr[8 * PW + tig + 4];
            }
#pragma unroll
            for (int nt = 0; nt < 2; ++nt) {
                const unsigned* vr = Vt + (wn * 16 + nt * 8 + g) * PW + kb * 8;
                unsigned b0 = vr[tig];
                unsigned b1 = vr[tig + 4];
                mma_f16(o[0][nt], a[0], b0, b1);
                mma_f16(o[1][nt], a[1], b0, b1);
            }
        }
    }

    // ---- O store ----
#pragma unroll
    for (int ms = 0; ms < 2; ++ms)
#pragma unroll
        for (int nt = 0; nt < 2; ++nt) {
            int row = wm * 32 + ms * 16 + g;
            int col = wn * 16 + nt * 8 + 2 * tig;
            float* og0 = out + ((size_t)bh * NSEQ + i0 + row) * 64 + col;
            float* og1 = out + ((size_t)bh * NSEQ + i0 + row + 8) * 64 + col;
            *(float2*)og0 = make_float2(o[ms][nt][0], o[ms][nt][1]);
            *(float2*)og1 = make_float2(o[ms][nt][2], o[ms][nt][3]);
        }
#undef PBUF
#undef VTBUF
}

extern "C" void kernel_launch(void* const* d_in, const int* in_sizes, int n_in,
                              void* d_out, int out_size) {
    const float* q = (const float*)d_in[0];
    const float* k = (const float*)d_in[1];
    const float* v = (const float*)d_in[2];
    const int* mask = (const int*)d_in[3];
    float* out = (float*)d_out;

    const int smem_bytes = SMEMW * 4;   // 85,760 B
    cudaFuncSetAttribute(lg16_kernel, cudaFuncAttributeMaxDynamicSharedMemorySize, smem_bytes);

    k_cvt<<<KVELEMS / 4 / 512, 512>>>(k);
    v_tr<<<dim3(NSEQ / 64, 16), 256>>>(v);
    dim3 grid(NSEQ / 128, 16);
    lg16_kernel<<<grid, 512, smem_bytes>>>(q, mask, out);
}

// round 17
// speedup vs baseline: 2.3533x; 1.1302x over previous
#include <cuda_runtime.h>
#include <cuda_fp16.h>
#include <cstdint>

#define NSEQ 2048
#define SCALEQ 0.18033688011112042f   // (1/sqrt(64)) * log2(e)
#define PW 36                          // smem row stride in 4B words (64 fp16 + 8 pad)

static const size_t ATT_OFF = 2097152;   // 16*2048*64

// smem WORD offsets
#define P0W   0        // Q stage / P buf0: 128 x PW
#define P1W   4608     // P buf1
#define KS0W  9216     // pass B K: 64 x PW
#define KS1W  11520
#define VT0W  13824    // Vt ring x3, stride 2304
#define MSKW  20736    // 64 u32
#define SLPW  20800    // 4 x 128 f32
#define RRIW  21312    // 128 f32
#define SMEMW 21440    // 85,760 B
// pass A mega-K buffers (128 rows x PW), aliasing pass-B-only regions:
#define KA0W  9216     // = KS0+KS1
#define KA1W  13824    // = VT0+VT1

#define KVELEMS (16 * 2048 * 64)
__device__ __half g_kh[KVELEMS];   // K as fp16, [bh][key][d]
__device__ __half g_vt[KVELEMS];   // V as fp16 TRANSPOSED, [bh][d][key]

__device__ __forceinline__ uint32_t smem_u32(const void* p) {
    uint32_t a;
    asm("{ .reg .u64 t; cvta.to.shared.u64 t, %1; cvt.u32.u64 %0, t; }" : "=r"(a) : "l"(p));
    return a;
}
__device__ __forceinline__ float ex2f_(float x) {
    float y; asm("ex2.approx.ftz.f32 %0, %1;" : "=f"(y) : "f"(x)); return y;
}
__device__ __forceinline__ unsigned h2bits(__half2 h) {
    return *reinterpret_cast<unsigned*>(&h);
}
__device__ __forceinline__ void mma_f16(float c[4], const unsigned a[4], unsigned b0, unsigned b1) {
    asm volatile(
        "mma.sync.aligned.m16n8k16.row.col.f32.f16.f16.f32 "
        "{%0,%1,%2,%3}, {%4,%5,%6,%7}, {%8,%9}, {%0,%1,%2,%3};"
        : "+f"(c[0]), "+f"(c[1]), "+f"(c[2]), "+f"(c[3])
        : "r"(a[0]), "r"(a[1]), "r"(a[2]), "r"(a[3]), "r"(b0), "r"(b1));
}
__device__ __forceinline__ void ldsm4(unsigned r[4], uint32_t a) {
    asm volatile("ldmatrix.sync.aligned.m8n8.x4.shared.b16 {%0,%1,%2,%3}, [%4];"
        : "=r"(r[0]), "=r"(r[1]), "=r"(r[2]), "=r"(r[3]) : "r"(a));
}

__device__ __forceinline__ void cp16(uint32_t dst, const void* src) {
    asm volatile("cp.async.cg.shared.global [%0], [%1], 16;" :: "r"(dst), "l"(src) : "memory");
}
#define CP_COMMIT() asm volatile("cp.async.commit_group;" ::: "memory")
#define CP_WAIT0()  asm volatile("cp.async.wait_group 0;" ::: "memory")

// =============== Kernel 0: K fp32->fp16  +  V fp32->fp16 transposed ===============
__global__ void __launch_bounds__(256, 4)
kv_prep(const float* __restrict__ k, const float* __restrict__ v) {
    __shared__ float ts[64][65];
    int bh = blockIdx.y, jt = blockIdx.x;
    int tid = threadIdx.x;

    // K convert: this tile's 64x64 elems (float4 granules)
    {
        const float4* src = (const float4*)(k + ((size_t)bh * NSEQ + jt * 64) * 64);
        uint2* dst = (uint2*)(g_kh + ((size_t)bh * NSEQ + jt * 64) * 64);
#pragma unroll
        for (int it = 0; it < 4; ++it) {
            int i4 = tid + it * 256;
            float4 t = src[i4];
            dst[i4] = make_uint2(h2bits(__floats2half2_rn(t.x, t.y)),
                                 h2bits(__floats2half2_rn(t.z, t.w)));
        }
    }

    // V transpose via smem
    const float* src = v + ((size_t)bh * NSEQ + jt * 64) * 64;
#pragma unroll
    for (int it = 0; it < 4; ++it) {
        int idx = tid + it * 256;
        int r = idx >> 4, c4 = (idx & 15) << 2;
        float4 t = *(const float4*)(src + r * 64 + c4);
        ts[r][c4] = t.x; ts[r][c4 + 1] = t.y; ts[r][c4 + 2] = t.z; ts[r][c4 + 3] = t.w;
    }
    __syncthreads();
    int d = tid >> 2, kg = (tid & 3) * 16;
    __half* dst = g_vt + (size_t)bh * 64 * NSEQ + (size_t)d * NSEQ + jt * 64 + kg;
#pragma unroll
    for (int kk = 0; kk < 16; kk += 2)
        *(__half2*)(dst + kk) = __floats2half2_rn(ts[kg + kk][d], ts[kg + kk + 1][d]);
}

// fp16 tile rows -> smem (8 x 16B chunks per row; dst stride 144B)
__device__ __forceinline__ void issue_rows64(uint32_t dstB, const __half* src, int srcStrideH, int tid) {
    int row = tid >> 3, ch = tid & 7;
    cp16(dstB + row * 144 + ch * 16, (const char*)src + (size_t)row * srcStrideH * 2 + ch * 16);
}
__device__ __forceinline__ void issue_rows128(uint32_t dstB, const __half* src, int tid) {
#pragma unroll
    for (int it = 0; it < 2; ++it) {
        int idx = tid + it * 512;
        int row = idx >> 3, ch = idx & 7;
        cp16(dstB + row * 144 + ch * 16, (const char*)src + (size_t)row * 128 + ch * 16);
    }
}

// S warp-tile via ldmatrix: kaddr = smem byte addr incl. keybase row offset + laneoffS
template <int NT>
__device__ __forceinline__ void compute_S_h(const unsigned aq[4][2][4], uint32_t kaddr,
                                            float c[2][NT][4]) {
#pragma unroll
    for (int ms = 0; ms < 2; ++ms)
#pragma unroll
        for (int nt = 0; nt < NT; ++nt)
#pragma unroll
            for (int e = 0; e < 4; ++e) c[ms][nt][e] = 0.f;
#pragma unroll
    for (int nt = 0; nt < NT; ++nt) {
        unsigned bql[8];
        ldsm4(bql, kaddr + nt * 1152);
        ldsm4(bql + 4, kaddr + nt * 1152 + 64);
#pragma unroll
        for (int ks = 0; ks < 4; ++ks) {
            mma_f16(c[0][nt], aq[ks][0], bql[2 * ks], bql[2 * ks + 1]);
            mma_f16(c[1][nt], aq[ks][1], bql[2 * ks], bql[2 * ks + 1]);
        }
    }
}

__global__ void __launch_bounds__(512, 1)
lg17_kernel(const float* __restrict__ q, const int* __restrict__ mask,
            float* __restrict__ out) {
    extern __shared__ float sm[];
    unsigned* smw = (unsigned*)sm;
    const uint32_t sbu = smem_u32(sm);
    const int tid = threadIdx.x;
    const int w = tid >> 5, lane = tid & 31;
    const int wm = w & 3, wn = w >> 2;           // 4 row groups x 4 key groups
    const int g = lane >> 2, tig = lane & 3;

    // ldmatrix per-lane address components
    const uint32_t laneoffS = (lane & 7) * 144 + (lane >> 3) * 16;                       // B-frag rows+chunks
    const uint32_t laneoffA = ((lane & 7) + ((lane >> 3) & 1) * 8) * 144 + (lane >> 4) * 16;  // A-frag
    const uint32_t laneoffVB = ((lane >> 4) * 8 + (lane & 7)) * 144 + ((lane >> 3) & 1) * 16; // PV B-frag

    const int bh = blockIdx.y, b = bh >> 2;      // H = 4
    const int i0 = blockIdx.x * 128;
    const float* qg = q + ((size_t)bh * NSEQ + i0) * 64;
    const __half* kg = g_kh + (size_t)bh * NSEQ * 64;
    const __half* vtg = g_vt + (size_t)bh * 64 * NSEQ;
    const int* mg = mask + (size_t)b * NSEQ;
    float* attg = out + ATT_OFF + ((size_t)bh * NSEQ + i0) * NSEQ;
    const unsigned* mw = smw + MSKW;

    // ---- prologue: Q (scaled, fp16) into P0 region; mask bitwords; K mega-tile 0 ----
#pragma unroll
    for (int it = 0; it < 4; ++it) {
        int idx = tid + it * 512;
        int r = idx >> 4, c4 = (idx & 15) << 2;
        float4 t = *(const float4*)(qg + r * 64 + c4);
        __half2 h0 = __floats2half2_rn(t.x * SCALEQ, t.y * SCALEQ);
        __half2 h1 = __floats2half2_rn(t.z * SCALEQ, t.w * SCALEQ);
        *(uint2*)(smw + P0W + r * PW + (c4 >> 1)) = make_uint2(h2bits(h0), h2bits(h1));
    }
    if (tid < 64) {
        unsigned bits = 0;
#pragma unroll 8
        for (int r = 0; r < 32; ++r) bits |= (mg[tid * 32 + r] != 0 ? 1u : 0u) << r;
        smw[MSKW + tid] = bits;
    }
    issue_rows128(sbu + KA0W * 4, kg, tid);
    CP_COMMIT();
    __syncthreads();

    // Q A-fragments register-resident (32 regs) via ldmatrix
    unsigned aq[4][2][4];
    {
        uint32_t qa = sbu + P0W * 4 + wm * 4608 + laneoffA;
#pragma unroll
        for (int ks = 0; ks < 4; ++ks)
#pragma unroll
            for (int ms = 0; ms < 2; ++ms)
                ldsm4(aq[ks][ms], qa + ms * 2304 + ks * 32);
    }

    // =================== Pass A: row sums, 128-key mega-tiles (16 iters) ===================
    float l[4] = {0.f, 0.f, 0.f, 0.f};   // slot s: row wm*32 + (s>>1)*16 + g + (s&1)*8
    for (int j = 0; j < 16; ++j) {
        CP_WAIT0();
        __syncthreads();
        if (j < 15) {
            issue_rows128(sbu + (((j + 1) & 1) ? KA1W : KA0W) * 4, kg + (size_t)(j + 1) * 128 * 64, tid);
            CP_COMMIT();
        }
        float c[2][4][4];
        compute_S_h<4>(aq, sbu + (((j & 1) ? KA1W : KA0W)) * 4 + wn * 4608 + laneoffS, c);

        unsigned wbits = mw[4 * j + wn];
#pragma unroll
        for (int ms = 0; ms < 2; ++ms)
#pragma unroll
            for (int nt = 0; nt < 4; ++nt) {
                int base = nt * 8 + 2 * tig;
                float e0 = ((wbits >> base) & 1u) ? ex2f_(c[ms][nt][0]) : 0.f;
                float e1 = ((wbits >> (base + 1)) & 1u) ? ex2f_(c[ms][nt][1]) : 0.f;
                float e2 = ((wbits >> base) & 1u) ? ex2f_(c[ms][nt][2]) : 0.f;
                float e3 = ((wbits >> (base + 1)) & 1u) ? ex2f_(c[ms][nt][3]) : 0.f;
                l[ms * 2] += e0 + e1;
                l[ms * 2 + 1] += e2 + e3;
            }
    }

    // K(0) prefetch (KS0 inside KA0; last mega-iter j=15 read KA1)
    issue_rows64(sbu + KS0W * 4, kg, 64, tid);
    CP_COMMIT();

    // reduce l: tig lanes, then wn groups via smem
#pragma unroll
    for (int s = 0; s < 4; ++s) {
        l[s] += __shfl_xor_sync(0xffffffffu, l[s], 1);
        l[s] += __shfl_xor_sync(0xffffffffu, l[s], 2);
    }
    if (tig == 0) {
#pragma unroll
        for (int s = 0; s < 4; ++s) {
            int row = wm * 32 + (s >> 1) * 16 + g + (s & 1) * 8;
            sm[SLPW + wn * 128 + row] = l[s];
        }
    }
    __syncthreads();   // all KA1 reads done -> Vt ring (aliasing it) writable
    issue_rows64(sbu + VT0W * 4, vtg, NSEQ, tid);
    CP_COMMIT();
    if (tid < 128) {
        float lt = sm[SLPW + tid] + sm[SLPW + 128 + tid] + sm[SLPW + 256 + tid] + sm[SLPW + 384 + tid];
        sm[RRIW + tid] = 1.0f / lt;
    }
    __syncthreads();

    float rri[4];
#pragma unroll
    for (int s = 0; s < 4; ++s)
        rri[s] = sm[RRIW + wm * 32 + (s >> 1) * 16 + g + (s & 1) * 8];

    // =================== Pass B: pipelined — iter j consumes P(j-1), produces P(j) ===================
    float o[2][2][4];
#pragma unroll
    for (int ms = 0; ms < 2; ++ms)
#pragma unroll
        for (int nt = 0; nt < 2; ++nt)
#pragma unroll
            for (int e = 0; e < 4; ++e) o[ms][nt][e] = 0.f;

#define PBUFW(jj) (((jj) & 1) ? P1W : P0W)
#define VTW(jj)   (VT0W + ((jj) % 3) * 2304)

    // ---- prologue iteration (j = 0): S(0), softmax, stage P(0) fp16 ----
    {
        CP_WAIT0();
        __syncthreads();   // K(0), Vt(0) arrived
        issue_rows64(sbu + KS1W * 4, kg + (size_t)64 * 64, 64, tid);
        issue_rows64(sbu + (VT0W + 2304) * 4, vtg + 64, NSEQ, tid);
        CP_COMMIT();

        float c[2][2][4];
        compute_S_h<2>(aq, sbu + KS0W * 4 + wn * 2304 + laneoffS, c);
        unsigned wbits = mw[wn >> 1];
        unsigned* Pb = smw + P0W;
#pragma unroll
        for (int ms = 0; ms < 2; ++ms)
#pragma unroll
            for (int nt = 0; nt < 2; ++nt) {
                int base = (wn & 1) * 16 + nt * 8 + 2 * tig;
                float p0 = ((wbits >> base) & 1u) ? ex2f_(c[ms][nt][0]) * rri[2 * ms] : 0.f;
                float p1 = ((wbits >> (base + 1)) & 1u) ? ex2f_(c[ms][nt][1]) * rri[2 * ms] : 0.f;
                float p2 = ((wbits >> base) & 1u) ? ex2f_(c[ms][nt][2]) * rri[2 * ms + 1] : 0.f;
                float p3 = ((wbits >> (base + 1)) & 1u) ? ex2f_(c[ms][nt][3]) * rri[2 * ms + 1] : 0.f;
                int wi = (wm * 32 + ms * 16 + g) * PW + 8 * wn + 4 * nt + tig;
                Pb[wi] = h2bits(__floats2half2_rn(p0, p1));
                Pb[wi + 8 * PW] = h2bits(__floats2half2_rn(p2, p3));
            }
    }

    // ---- main loop: j = 1..31 ----
    for (int j = 1; j < 32; ++j) {
        CP_WAIT0();
        __syncthreads();   // K/Vt(j) arrived; P(j-1) visible; P buf (j&1) free

        if (j < 31) {
            issue_rows64(sbu + (((j + 1) & 1) ? KS1W : KS0W) * 4, kg + (size_t)(j + 1) * 64 * 64, 64, tid);
            issue_rows64(sbu + (VT0W + ((j + 1) % 3) * 2304) * 4, vtg + (j + 1) * 64, NSEQ, tid);
            CP_COMMIT();
        }

        const unsigned* Pp = smw + PBUFW(j - 1);

        // attention store for tile j-1: fp16 -> fp32, coalesced 256B row segments
#pragma unroll
        for (int it = 0; it < 2; ++it) {
            int idx = tid + it * 512;
            int row = idx >> 3, grp = idx & 7;
            uint4 wv = *(const uint4*)(Pp + row * PW + grp * 4);
            float2 f0 = __half22float2(*(__half2*)&wv.x);
            float2 f1 = __half22float2(*(__half2*)&wv.y);
            float2 f2 = __half22float2(*(__half2*)&wv.z);
            float2 f3 = __half22float2(*(__half2*)&wv.w);
            float* ab = attg + (size_t)row * NSEQ + (j - 1) * 64 + grp * 8;
            *(float4*)ab = make_float4(f0.x, f0.y, f1.x, f1.y);
            *(float4*)(ab + 4) = make_float4(f2.x, f2.y, f3.x, f3.y);
        }

        // PV(j-1): ldmatrix A (P) + ldmatrix B (Vt)
        {
            uint32_t pa = sbu + PBUFW(j - 1) * 4 + wm * 4608 + laneoffA;
            uint32_t va = sbu + VTW(j - 1) * 4 + wn * 2304 + laneoffVB;
#pragma unroll
            for (int kb = 0; kb < 4; ++kb) {
                unsigned a0[4], a1[4], bv[4];
                ldsm4(a0, pa + kb * 32);
                ldsm4(a1, pa + 2304 + kb * 32);
                ldsm4(bv, va + kb * 32);
                mma_f16(o[0][0], a0, bv[0], bv[1]);
                mma_f16(o[1][0], a1, bv[0], bv[1]);
                mma_f16(o[0][1], a0, bv[2], bv[3]);
                mma_f16(o[1][1], a1, bv[2], bv[3]);
            }
        }

        // S(j) + softmax + stage P(j) fp16
        {
            float c[2][2][4];
            compute_S_h<2>(aq, sbu + (((j & 1) ? KS1W : KS0W)) * 4 + wn * 2304 + laneoffS, c);
            unsigned wbits = mw[2 * j + (wn >> 1)];
            unsigned* Pb = smw + PBUFW(j);
#pragma unroll
            for (int ms = 0; ms < 2; ++ms)
#pragma unroll
                for (int nt = 0; nt < 2; ++nt) {
                    int base = (wn & 1) * 16 + nt * 8 + 2 * tig;
                    float p0 = ((wbits >> base) & 1u) ? ex2f_(c[ms][nt][0]) * rri[2 * ms] : 0.f;
                    float p1 = ((wbits >> (base + 1)) & 1u) ? ex2f_(c[ms][nt][1]) * rri[2 * ms] : 0.f;
                    float p2 = ((wbits >> base) & 1u) ? ex2f_(c[ms][nt][2]) * rri[2 * ms + 1] : 0.f;
                    float p3 = ((wbits >> (base + 1)) & 1u) ? ex2f_(c[ms][nt][3]) * rri[2 * ms + 1] : 0.f;
                    int wi = (wm * 32 + ms * 16 + g) * PW + 8 * wn + 4 * nt + tig;
                    Pb[wi] = h2bits(__floats2half2_rn(p0, p1));
                    Pb[wi + 8 * PW] = h2bits(__floats2half2_rn(p2, p3));
                }
        }
    }

    // ---- epilogue: consume P(31) ----
    __syncthreads();
    {
        const unsigned* Pp = smw + PBUFW(31);
#pragma unroll
        for (int it = 0; it < 2; ++it) {
            int idx = tid + it * 512;
            int row = idx >> 3, grp = idx & 7;
            uint4 wv = *(const uint4*)(Pp + row * PW + grp * 4);
            float2 f0 = __half22float2(*(__half2*)&wv.x);
            float2 f1 = __half22float2(*(__half2*)&wv.y);
            float2 f2 = __half22float2(*(__half2*)&wv.z);
            float2 f3 = __half22float2(*(__half2*)&wv.w);
            float* ab = attg + (size_t)row * NSEQ + 31 * 64 + grp * 8;
            *(float4*)ab = make_float4(f0.x, f0.y, f1.x, f1.y);
            *(float4*)(ab + 4) = make_float4(f2.x, f2.y, f3.x, f3.y);
        }
        uint32_t pa = sbu + PBUFW(31) * 4 + wm * 4608 + laneoffA;
        uint32_t va = sbu + VTW(31) * 4 + wn * 2304 + laneoffVB;
#pragma unroll
        for (int kb = 0; kb < 4; ++kb) {
            unsigned a0[4], a1[4], bv[4];
            ldsm4(a0, pa + kb * 32);
            ldsm4(a1, pa + 2304 + kb * 32);
            ldsm4(bv, va + kb * 32);
            mma_f16(o[0][0], a0, bv[0], bv[1]);
            mma_f16(o[1][0], a1, bv[0], bv[1]);
            mma_f16(o[0][1], a0, bv[2], bv[3]);
            mma_f16(o[1][1], a1, bv[2], bv[3]);
        }
    }

    // ---- O store ----
#pragma unroll
    for (int ms = 0; ms < 2; ++ms)
#pragma unroll
        for (int nt = 0; nt < 2; ++nt) {
            int row = wm * 32 + ms * 16 + g;
            int col = wn * 16 + nt * 8 + 2 * tig;
            float* og0 = out + ((size_t)bh * NSEQ + i0 + row) * 64 + col;
            float* og1 = out + ((size_t)bh * NSEQ + i0 + row + 8) * 64 + col;
            *(float2*)og0 = make_float2(o[ms][nt][0], o[ms][nt][1]);
            *(float2*)og1 = make_float2(o[ms][nt][2], o[ms][nt][3]);
        }
#undef PBUFW
#undef VTW
}

extern "C" void kernel_launch(void* const* d_in, const int* in_sizes, int n_in,
                              void* d_out, int out_size) {
    const float* q = (const float*)d_in[0];
    const float* k = (const float*)d_in[1];
    const float* v = (const float*)d_in[2];
    const int* mask = (const int*)d_in[3];
    float* out = (float*)d_out;

    const int smem_bytes = SMEMW * 4;   // 85,760 B
    cudaFuncSetAttribute(lg17_kernel, cudaFuncAttributeMaxDynamicSharedMemorySize, smem_bytes);

    kv_prep<<<dim3(NSEQ / 64, 16), 256>>>(k, v);
    dim3 grid(NSEQ / 128, 16);
    lg17_kernel<<<grid, 512, smem_bytes>>>(q, mask, out);
}